// round 11
// baseline (speedup 1.0000x reference)
#include <cuda_runtime.h>
#include <cuda_pipeline.h>

// Per-WARP private cp.async pipelines: no CTA barriers in the streaming loop.
// Each warp owns 2 stages x 2 arrays x 1536B smem and streams 384-float
// warp-tiles coalesced (lane-stride 16B); compute reads lane-local 48B.
// Warp progress is decoupled -> no convoy on the slowest warp.

#define GRID    608              // 152 SMs * 4 CTAs (48KB smem/CTA)
#define BLOCK   256
#define WARPS   8
#define WTILE_B 1536             // bytes per array per warp-tile (384 floats)
#define GSTRIDE (GRID * WARPS)   // 4864 warp-tiles per grid iteration

__device__ float        g_partials[GRID];
__device__ unsigned int g_ticket = 0;

__global__ void __launch_bounds__(BLOCK)
dist_mean_kernel(const char* __restrict__ pbase, const char* __restrict__ tbase,
                 int ntiles, int n_elem, double inv_count,
                 float* __restrict__ out)
{
    // [warp][stage][array][bytes] = 8*2*2*1536 = 49152 B (static smem max)
    __shared__ alignas(16) char sbuf[WARPS][2][2][WTILE_B];

    const int tid = threadIdx.x;
    const int wid = tid >> 5;
    const int lid = tid & 31;
    float acc = 0.0f;

    // ---- remainder floats beyond ntiles*384 (zero for this shape; safety) ----
    {
        const int rem_trip = (n_elem - ntiles * 384) / 3;
        if (blockIdx.x == 0 && rem_trip > 0) {
            const float* pf = (const float*)pbase + ntiles * 384;
            const float* tf = (const float*)tbase + ntiles * 384;
            for (int i = tid; i < rem_trip; i += BLOCK) {
                float a = pf[3*i+0] - tf[3*i+0];
                float b = pf[3*i+1] - tf[3*i+1];
                float c = pf[3*i+2] - tf[3*i+2];
                acc += sqrtf(fmaf(a, a, fmaf(b, b, c * c)));
            }
        }
    }

    const int gw = blockIdx.x * WARPS + wid;   // global warp id

    // ---- prologue: prefetch first warp-tile into stage 0 ----
    int t = gw;
    if (t < ntiles) {
        const char* gp = pbase + (size_t)t * WTILE_B + lid * 16;
        const char* gt = tbase + (size_t)t * WTILE_B + lid * 16;
        #pragma unroll
        for (int j = 0; j < 3; j++) {
            __pipeline_memcpy_async(&sbuf[wid][0][0][lid*16 + j*512], gp + j*512, 16);
            __pipeline_memcpy_async(&sbuf[wid][0][1][lid*16 + j*512], gt + j*512, 16);
        }
    }
    __pipeline_commit();

    // ---- per-warp streaming pipeline (no __syncthreads) ----
    int s = 0;
    for (; t < ntiles; t += GSTRIDE, s ^= 1) {
        __syncwarp();                          // WAR: prior compute done reading s^1
        const int nxt = t + GSTRIDE;
        if (nxt < ntiles) {
            const char* gp = pbase + (size_t)nxt * WTILE_B + lid * 16;
            const char* gt = tbase + (size_t)nxt * WTILE_B + lid * 16;
            #pragma unroll
            for (int j = 0; j < 3; j++) {
                __pipeline_memcpy_async(&sbuf[wid][s^1][0][lid*16 + j*512], gp + j*512, 16);
                __pipeline_memcpy_async(&sbuf[wid][s^1][1][lid*16 + j*512], gt + j*512, 16);
            }
        }
        __pipeline_commit();                   // exactly one group per iteration
        __pipeline_wait_prior(1);              // stage s landed (this thread's copies)
        __syncwarp();                          // cross-lane visibility within warp

        // compute: 12 consecutive floats = 4 triplets per lane (conflict-free LDS)
        const float4* ps = (const float4*)&sbuf[wid][s][0][lid * 48];
        const float4* ts = (const float4*)&sbuf[wid][s][1][lid * 48];
        float4 p0 = ps[0], p1 = ps[1], p2 = ps[2];
        float4 t0 = ts[0], t1 = ts[1], t2 = ts[2];

        float a, b, c;
        a = p0.x - t0.x; b = p0.y - t0.y; c = p0.z - t0.z;
        acc += sqrtf(fmaf(a, a, fmaf(b, b, c * c)));
        a = p0.w - t0.w; b = p1.x - t1.x; c = p1.y - t1.y;
        acc += sqrtf(fmaf(a, a, fmaf(b, b, c * c)));
        a = p1.z - t1.z; b = p1.w - t1.w; c = p2.x - t2.x;
        acc += sqrtf(fmaf(a, a, fmaf(b, b, c * c)));
        a = p2.y - t2.y; b = p2.z - t2.z; c = p2.w - t2.w;
        acc += sqrtf(fmaf(a, a, fmaf(b, b, c * c)));
    }

    // ---- block reduce (scratch aliased into sbuf; all pipelines drained) ----
    __syncthreads();
    float*  sm_f  = (float*)&sbuf[0][0][0][0];
    int*    sm_fl = (int*)&sbuf[0][0][0][64];
    double* sm_d  = (double*)&sbuf[0][0][0][128];

    #pragma unroll
    for (int o = 16; o > 0; o >>= 1)
        acc += __shfl_down_sync(0xffffffffu, acc, o);
    if (lid == 0) sm_f[wid] = acc;
    __syncthreads();

    if (tid < 32) {
        float v = (tid < WARPS) ? sm_f[tid] : 0.0f;
        #pragma unroll
        for (int o = 4; o > 0; o >>= 1)
            v += __shfl_down_sync(0xffffffffu, v, o);
        if (tid == 0) {
            g_partials[blockIdx.x] = v;
            __threadfence();
            unsigned int tk = atomicInc(&g_ticket, GRID - 1);
            sm_fl[0] = (tk == GRID - 1) ? 1 : 0;
        }
    }
    __syncthreads();
    if (!sm_fl[0]) return;

    // ---- last block: deterministic final reduce ----
    double dacc = 0.0;
    #pragma unroll
    for (int i = tid; i < GRID; i += BLOCK)
        dacc += (double)g_partials[i];

    #pragma unroll
    for (int o = 16; o > 0; o >>= 1)
        dacc += __shfl_down_sync(0xffffffffu, dacc, o);
    if (lid == 0) sm_d[wid] = dacc;
    __syncthreads();

    if (tid == 0) {
        double v = 0.0;
        #pragma unroll
        for (int i = 0; i < WARPS; i++) v += sm_d[i];
        out[0] = (float)(v * inv_count);
    }
}

extern "C" void kernel_launch(void* const* d_in, const int* in_sizes, int n_in,
                              void* d_out, int out_size)
{
    const char* pred = (const char*)d_in[0];
    const char* targ = (const char*)d_in[1];
    float* out = (float*)d_out;

    const int n_elem = in_sizes[0];            // B*63 = 66,060,288 = 384 * 172,032
    const int ntiles = n_elem / 384;           // exact for this shape
    const long long n_dists = (long long)n_elem / 3;
    const double inv_cnt = 1.0 / (double)n_dists;

    dist_mean_kernel<<<GRID, BLOCK>>>(pred, targ, ntiles, n_elem, inv_cnt, out);
}

// round 13
// speedup vs baseline: 1.0781x; 1.0781x over previous
#include <cuda_runtime.h>
#include <cuda_pipeline.h>

// R10 structure (CTA-wide coalesced cp.async tiles) upgraded to a 3-stage
// ring in dynamic smem: ONE __syncthreads per iteration (prefetch target
// stage was last read a full barrier ago) and TWO tiles in flight.
// 72KB/CTA -> 3 CTAs/SM, GRID = 152*3 = 456 = one wave.

#define GRID       456
#define BLOCK      256
#define TILE_F     3072             // floats per array per tile
#define TILE_BYTES 12288            // bytes  per array per tile
#define STAGES     3
#define SMEM_DYN   (STAGES * 2 * TILE_BYTES)   // 73728 B

__device__ float        g_partials[GRID];
__device__ unsigned int g_ticket = 0;

extern __shared__ char sbuf[];      // [stage][arr][TILE_BYTES]

__device__ __forceinline__ char* stg(int s, int arr) {
    return sbuf + (s * 2 + arr) * TILE_BYTES;
}

__global__ void __launch_bounds__(BLOCK)
dist_mean_kernel(const char* __restrict__ pbase, const char* __restrict__ tbase,
                 int ntiles, int n_elem, double inv_count,
                 float* __restrict__ out)
{
    const int tid = threadIdx.x;
    float acc = 0.0f;

    // ---- remainder triplets beyond ntiles*TILE_F (zero for this shape) ----
    {
        const int rem_trip = (n_elem - ntiles * TILE_F) / 3;
        if (blockIdx.x == 0 && rem_trip > 0) {
            const float* pf = (const float*)pbase + ntiles * TILE_F;
            const float* tf = (const float*)tbase + ntiles * TILE_F;
            for (int i = tid; i < rem_trip; i += BLOCK) {
                float a = pf[3*i+0] - tf[3*i+0];
                float b = pf[3*i+1] - tf[3*i+1];
                float c = pf[3*i+2] - tf[3*i+2];
                acc += sqrtf(fmaf(a, a, fmaf(b, b, c * c)));
            }
        }
    }

    // ---- prologue: prefetch tiles t0,t1 into stages 0,1 (one group each) ----
    #pragma unroll
    for (int k = 0; k < STAGES - 1; k++) {
        const int tile = blockIdx.x + k * GRID;
        if (tile < ntiles) {
            const char* gp = pbase + (size_t)tile * TILE_BYTES + tid * 16;
            const char* gt = tbase + (size_t)tile * TILE_BYTES + tid * 16;
            #pragma unroll
            for (int j = 0; j < 3; j++) {
                __pipeline_memcpy_async(stg(k, 0) + tid*16 + j*4096, gp + j*4096, 16);
                __pipeline_memcpy_async(stg(k, 1) + tid*16 + j*4096, gt + j*4096, 16);
            }
        }
        __pipeline_commit();
    }

    // ---- main loop: ONE barrier per iteration, two tiles in flight ----
    int s = 0;
    for (int t = blockIdx.x; t < ntiles; t += GRID) {
        __pipeline_wait_prior(STAGES - 2);     // tile t landed (this thread's part)
        __syncthreads();                        // visible to all; iter t-1 compute done
                                                // -> safe to overwrite stage s+2 (== s-1)
        int sp = s + 2; if (sp >= STAGES) sp -= STAGES;
        const int pf = t + 2 * GRID;
        if (pf < ntiles) {
            const char* gp = pbase + (size_t)pf * TILE_BYTES + tid * 16;
            const char* gt = tbase + (size_t)pf * TILE_BYTES + tid * 16;
            #pragma unroll
            for (int j = 0; j < 3; j++) {
                __pipeline_memcpy_async(stg(sp, 0) + tid*16 + j*4096, gp + j*4096, 16);
                __pipeline_memcpy_async(stg(sp, 1) + tid*16 + j*4096, gt + j*4096, 16);
            }
        }
        __pipeline_commit();                    // exactly one group per iteration

        // compute: 12 consecutive floats = 4 triplets per thread (conflict-free)
        const float4* ps = (const float4*)(stg(s, 0) + tid * 48);
        const float4* ts = (const float4*)(stg(s, 1) + tid * 48);
        float4 p0 = ps[0], p1 = ps[1], p2 = ps[2];
        float4 t0 = ts[0], t1 = ts[1], t2 = ts[2];

        float a, b, c;
        a = p0.x - t0.x; b = p0.y - t0.y; c = p0.z - t0.z;
        acc += sqrtf(fmaf(a, a, fmaf(b, b, c * c)));
        a = p0.w - t0.w; b = p1.x - t1.x; c = p1.y - t1.y;
        acc += sqrtf(fmaf(a, a, fmaf(b, b, c * c)));
        a = p1.z - t1.z; b = p1.w - t1.w; c = p2.x - t2.x;
        acc += sqrtf(fmaf(a, a, fmaf(b, b, c * c)));
        a = p2.y - t2.y; b = p2.z - t2.z; c = p2.w - t2.w;
        acc += sqrtf(fmaf(a, a, fmaf(b, b, c * c)));

        s = (s + 1 == STAGES) ? 0 : s + 1;
    }

    // ---- drain pipeline, then reuse smem as reduction scratch ----
    __pipeline_wait_prior(0);
    __syncthreads();

    float*  sm_f  = (float*)(sbuf + 0);
    int*    sm_fl = (int*)(sbuf + 64);
    double* sm_d  = (double*)(sbuf + 128);

    #pragma unroll
    for (int o = 16; o > 0; o >>= 1)
        acc += __shfl_down_sync(0xffffffffu, acc, o);
    if ((tid & 31) == 0) sm_f[tid >> 5] = acc;
    __syncthreads();

    if (tid < 32) {
        float v = (tid < BLOCK / 32) ? sm_f[tid] : 0.0f;
        #pragma unroll
        for (int o = 4; o > 0; o >>= 1)
            v += __shfl_down_sync(0xffffffffu, v, o);
        if (tid == 0) {
            g_partials[blockIdx.x] = v;
            __threadfence();
            unsigned int tk = atomicInc(&g_ticket, GRID - 1);
            sm_fl[0] = (tk == GRID - 1) ? 1 : 0;
        }
    }
    __syncthreads();
    if (!sm_fl[0]) return;

    // ---- last block: deterministic final reduce ----
    double dacc = 0.0;
    #pragma unroll
    for (int i = tid; i < GRID; i += BLOCK)
        dacc += (double)g_partials[i];

    #pragma unroll
    for (int o = 16; o > 0; o >>= 1)
        dacc += __shfl_down_sync(0xffffffffu, dacc, o);
    if ((tid & 31) == 0) sm_d[tid >> 5] = dacc;
    __syncthreads();

    if (tid == 0) {
        double v = 0.0;
        #pragma unroll
        for (int i = 0; i < BLOCK / 32; i++) v += sm_d[i];
        out[0] = (float)(v * inv_count);
    }
}

extern "C" void kernel_launch(void* const* d_in, const int* in_sizes, int n_in,
                              void* d_out, int out_size)
{
    const char* pred = (const char*)d_in[0];
    const char* targ = (const char*)d_in[1];
    float* out = (float*)d_out;

    static int attr_done = 0;
    if (!attr_done) {
        cudaFuncSetAttribute(dist_mean_kernel,
                             cudaFuncAttributeMaxDynamicSharedMemorySize, SMEM_DYN);
        attr_done = 1;
    }

    const int n_elem = in_sizes[0];            // B*63 = 66,060,288 = 3072 * 21504
    const int ntiles = n_elem / TILE_F;
    const long long n_dists = (long long)n_elem / 3;
    const double inv_cnt = 1.0 / (double)n_dists;

    dist_mean_kernel<<<GRID, BLOCK, SMEM_DYN>>>(pred, targ, ntiles, n_elem,
                                                inv_cnt, out);
}